// round 6
// baseline (speedup 1.0000x reference)
#include <cuda_runtime.h>

// Problem constants (fixed by the reference)
#define SEQ_LEN   512
#define EMB       768
#define NLAB      9
#define FEAT      2354            // 3*768 + 50
#define WDIM      50
#define MAXW      16
#define NSPANS    32768
#define NCHUNK    6               // 768 / 128
#define CHUNK     128
#define JPAD      28              // 27 dots padded to 28 for float4 reduce

// Packed tables (allocation-free rule: __device__ globals)
// g_S[t*9+l] = (Ps[t][l], Pc[t][l])   Pc[t] = exclusive prefix of Pa
// g_E[t*9+l] = (Pe[t][l], Pc[t][l])
// g_Wb[w*9+l] = (width_proj + bias, 1/w)
__device__ float  g_part[NCHUNK * SEQ_LEN * JPAD];
__device__ float2 g_S[SEQ_LEN * NLAB];
__device__ float2 g_E[SEQ_LEN * NLAB];
__device__ float2 g_Wb[(MAXW + 1) * NLAB];
__device__ unsigned g_ticket = 0;   // last-block resets -> graph-replay safe

// ---------------------------------------------------------------------------
// K1: split-K token projection, grid (64 token-groups, 6 k-chunks) x 256thr.
// Block stages its 27x128-float W chunk in smem (8x reuse), warp-per-token
// dot products, partials out. LAST block (ticket, no spinning) then does:
// width table + float4 partial reduction + 9-label scan over 512 tokens.
// ---------------------------------------------------------------------------
__global__ void __launch_bounds__(256)
proj_kernel(const float* __restrict__ seq,
            const float* __restrict__ wt,
            const float* __restrict__ W,
            const float* __restrict__ b) {
    // union: staging (3456 floats) aliases tail's Pa (4608) + scan temps (144)
    __shared__ __align__(16) float smem_buf[SEQ_LEN * NLAB + 2 * 8 * NLAB];
    __shared__ bool s_last;

    const int tid  = threadIdx.x;
    const int warp = tid >> 5;
    const int lane = tid & 31;
    const int chunk = blockIdx.y;
    const int kbase = chunk * CHUNK;
    const int tok   = blockIdx.x * 8 + warp;

    float* sw = smem_buf;   // 27 x 128 staging

    // Stage W chunk: 27 rows x 128 floats (float2: rows 8B-aligned).
    for (int i = tid; i < 27 * (CHUNK / 2); i += 256) {
        const int j = i >> 6;                 // 0..26
        const int p = (i & 63) * 2;           // 0..126
        const int l = j % 9, sl = j / 9;
        const float2 v = __ldg(reinterpret_cast<const float2*>(
            W + (size_t)l * FEAT + sl * EMB + kbase + p));
        sw[j * CHUNK + p]     = v.x;
        sw[j * CHUNK + p + 1] = v.y;
    }
    __syncthreads();

    const float4 sv = *reinterpret_cast<const float4*>(
        seq + (size_t)tok * EMB + kbase + lane * 4);

    float acc[27];
    #pragma unroll
    for (int j = 0; j < 27; j++) {
        const float4 w4 = *reinterpret_cast<const float4*>(sw + j * CHUNK + lane * 4);
        acc[j] = sv.x * w4.x + sv.y * w4.y + sv.z * w4.z + sv.w * w4.w;
    }
    #pragma unroll
    for (int j = 0; j < 27; j++) {
        #pragma unroll
        for (int o = 16; o > 0; o >>= 1)
            acc[j] += __shfl_down_sync(0xffffffffu, acc[j], o);
    }
    if (lane == 0) {
        float* dst = g_part + ((size_t)chunk * SEQ_LEN + tok) * JPAD;
        #pragma unroll
        for (int j = 0; j < 27; j++) dst[j] = acc[j];
    }

    // ---- last-block ticket (release/acquire, zero spinning) ---------------
    __threadfence();
    __syncthreads();            // also guards smem_buf reuse below
    if (tid == 0)
        s_last = (atomicAdd(&g_ticket, 1) == (unsigned)(gridDim.x * gridDim.y - 1));
    __syncthreads();
    if (!s_last) return;

    if (tid == 0) g_ticket = 0;       // reset for next graph replay
    __threadfence();                  // acquire all blocks' partial writes

    float* sPa   = smem_buf;                      // [512][9]
    float* tot   = smem_buf + SEQ_LEN * NLAB;     // [8][9]
    float* carry = tot + 8 * NLAB;                // [8][9]

    // Width table + per-width reciprocal.
    if (tid < (MAXW + 1) * NLAB) {
        const int w = tid / NLAB;
        const int l = tid % NLAB;
        const float* wrow = W + (size_t)l * FEAT + 3 * EMB;
        float a = __ldg(b + l);
        #pragma unroll
        for (int k = 0; k < WDIM; k++)
            a += __ldg(wt + w * WDIM + k) * __ldg(wrow + k);
        g_Wb[tid] = make_float2(a, 1.0f / (float)w);   // w=0 never read
    }

    // Reduce partials: 512 tokens x 7 float4-groups, 6 chunks each (MLP=6/iter,
    // 14 iters/thread in flight). __ldcg: L2-fresh cross-block reads.
    for (int i = tid; i < SEQ_LEN * (JPAD / 4); i += 256) {
        const int t = i / (JPAD / 4);
        const int q = i - t * (JPAD / 4);
        float4 s = make_float4(0.f, 0.f, 0.f, 0.f);
        #pragma unroll
        for (int c = 0; c < NCHUNK; c++) {
            const float4 v = __ldcg(reinterpret_cast<const float4*>(
                g_part + ((size_t)c * SEQ_LEN + t) * JPAD + q * 4));
            s.x += v.x; s.y += v.y; s.z += v.z; s.w += v.w;
        }
        const float vv[4] = {s.x, s.y, s.z, s.w};
        #pragma unroll
        for (int k = 0; k < 4; k++) {
            const int j = q * 4 + k;
            if (j < 27) {
                const int sl = j / 9, l = j - sl * 9;
                if (sl == 0)
                    reinterpret_cast<float*>(g_S)[(t * NLAB + l) * 2] = vv[k];
                else if (sl == 1)
                    reinterpret_cast<float*>(g_E)[(t * NLAB + l) * 2] = vv[k];
                else
                    sPa[t * NLAB + l] = vv[k];
            }
        }
    }
    __syncthreads();

    // 9 parallel scans over 512 tokens (thread = 2 tokens).
    const int t0 = tid * 2;
    float a0[NLAB], pr[NLAB], inc[NLAB];
    #pragma unroll
    for (int l = 0; l < NLAB; l++) {
        a0[l] = sPa[t0 * NLAB + l];
        pr[l] = a0[l] + sPa[(t0 + 1) * NLAB + l];
    }
    #pragma unroll
    for (int l = 0; l < NLAB; l++) {
        float x = pr[l];
        #pragma unroll
        for (int o = 1; o < 32; o <<= 1) {
            const float y = __shfl_up_sync(0xffffffffu, x, o);
            if (lane >= o) x += y;
        }
        inc[l] = x;
    }
    if (lane == 31) {
        #pragma unroll
        for (int l = 0; l < NLAB; l++) tot[warp * NLAB + l] = inc[l];
    }
    __syncthreads();
    if (tid < NLAB) {
        float r = 0.f;
        #pragma unroll
        for (int w = 0; w < 8; w++) { carry[w * NLAB + tid] = r; r += tot[w * NLAB + tid]; }
    }
    __syncthreads();
    #pragma unroll
    for (int l = 0; l < NLAB; l++) {
        const float pc0 = inc[l] - pr[l] + carry[warp * NLAB + l];  // Pc[t0]
        const float pc1 = pc0 + a0[l];                              // Pc[t0+1]
        reinterpret_cast<float*>(g_S)[(t0 * NLAB + l) * 2 + 1] = pc0;
        reinterpret_cast<float*>(g_E)[(t0 * NLAB + l) * 2 + 1] = pc0;
        reinterpret_cast<float*>(g_S)[((t0 + 1) * NLAB + l) * 2 + 1] = pc1;
        reinterpret_cast<float*>(g_E)[((t0 + 1) * NLAB + l) * 2 + 1] = pc1;
    }
}

// ---------------------------------------------------------------------------
// K2: assemble logits. Block = 288 threads = 32 spans x 9 labels (exact
// cover, no runtime div for span). Coalesced stores; idx loads broadcast;
// table lookups L1-resident after first touch.
// ---------------------------------------------------------------------------
__global__ void __launch_bounds__(288)
assemble_kernel(const int* __restrict__ st,
                const int* __restrict__ en,
                const int* __restrict__ wd,
                float* __restrict__ out) {
    const int tid  = threadIdx.x;
    const int sp_l = tid / NLAB;                 // 0..31
    const int l    = tid - sp_l * NLAB;          // 0..8
    const int span = blockIdx.x * 32 + sp_l;

    const int s = __ldg(st + span);
    const int e = __ldg(en + span);
    const int w = __ldg(wd + span);
    const float2 fs = g_S[s * NLAB + l];
    const float2 fe = g_E[e * NLAB + l];
    const float2 fw = g_Wb[w * NLAB + l];
    out[blockIdx.x * 288 + tid] = fs.x + fe.x + (fe.y - fs.y) * fw.y + fw.x;
}

// ---------------------------------------------------------------------------
extern "C" void kernel_launch(void* const* d_in, const int* in_sizes, int n_in,
                              void* d_out, int out_size) {
    const float* seq = (const float*)d_in[0];   // [1,512,768]
    const int*   st  = (const int*)  d_in[1];   // [32768]
    const int*   en  = (const int*)  d_in[2];   // [32768]
    const int*   wd  = (const int*)  d_in[3];   // [32768]
    const float* wt  = (const float*)d_in[4];   // [17,50]
    const float* W   = (const float*)d_in[5];   // [9,2354]
    const float* b   = (const float*)d_in[6];   // [9]
    float* out = (float*)d_out;                 // [32768,9]

    dim3 g1(SEQ_LEN / 8, NCHUNK);               // 384 blocks
    proj_kernel<<<g1, 256>>>(seq, wt, W, b);
    assemble_kernel<<<NSPANS / 32, 288>>>(st, en, wd, out);
}

// round 7
// speedup vs baseline: 1.1377x; 1.1377x over previous
#include <cuda_runtime.h>

// Problem constants (fixed by the reference)
#define SEQ_LEN   512
#define EMB       768
#define NLAB      9
#define FEAT      2354            // 3*768 + 50
#define WDIM      50
#define MAXW      16
#define NSPANS    32768
#define NCHUNK    6               // 768 / 128
#define CHUNK     128
#define JPAD      28              // 27 dots padded to 28 (=7 float4)
#define Q4        7               // JPAD/4
#define FLAT4     (SEQ_LEN * Q4)  // 3584 float4 per chunk

// Packed tables (allocation-free rule: __device__ globals)
// g_S[t*9+l] = (Ps[t][l], Pc[t][l])   Pc = exclusive prefix of Pa
// g_E[t*9+l] = (Pe[t][l], Pc[t][l])
// g_Wb[w*9+l] = (width_proj + bias, 1/w)
__device__ float4 g_part4[NCHUNK * FLAT4];
__device__ float2 g_S[SEQ_LEN * NLAB];
__device__ float2 g_E[SEQ_LEN * NLAB];
__device__ float2 g_Wb[(MAXW + 1) * NLAB];

// ---------------------------------------------------------------------------
// K1: split-K token projection (= R3's proven config).
// grid (64 token-groups, 6 k-chunks) x 256 thr. Block stages its 27x128 W
// chunk in smem (8x reuse), warp-per-token dots, shfl-reduce, partials out.
// ---------------------------------------------------------------------------
__global__ void __launch_bounds__(256)
proj_kernel(const float* __restrict__ seq, const float* __restrict__ W) {
    __shared__ __align__(16) float sw[27 * CHUNK];

    const int tid   = threadIdx.x;
    const int warp  = tid >> 5;
    const int lane  = tid & 31;
    const int chunk = blockIdx.y;
    const int kbase = chunk * CHUNK;
    const int tok   = blockIdx.x * 8 + warp;

    for (int i = tid; i < 27 * (CHUNK / 2); i += 256) {
        const int j = i >> 6;                 // 0..26
        const int p = (i & 63) * 2;           // 0..126
        const int l = j % 9, sl = j / 9;
        const float2 v = __ldg(reinterpret_cast<const float2*>(
            W + (size_t)l * FEAT + sl * EMB + kbase + p));
        sw[j * CHUNK + p]     = v.x;
        sw[j * CHUNK + p + 1] = v.y;
    }
    __syncthreads();

    const float4 sv = *reinterpret_cast<const float4*>(
        seq + (size_t)tok * EMB + kbase + lane * 4);

    float acc[27];
    #pragma unroll
    for (int j = 0; j < 27; j++) {
        const float4 w4 = *reinterpret_cast<const float4*>(sw + j * CHUNK + lane * 4);
        acc[j] = sv.x * w4.x + sv.y * w4.y + sv.z * w4.z + sv.w * w4.w;
    }
    #pragma unroll
    for (int j = 0; j < 27; j++) {
        #pragma unroll
        for (int o = 16; o > 0; o >>= 1)
            acc[j] += __shfl_down_sync(0xffffffffu, acc[j], o);
    }
    if (lane == 0) {
        float* dst = reinterpret_cast<float*>(g_part4)
                   + ((size_t)chunk * SEQ_LEN + tok) * JPAD;
        #pragma unroll
        for (int j = 0; j < 27; j++) dst[j] = acc[j];
        dst[27] = 0.f;                        // keep pad finite
    }
}

// ---------------------------------------------------------------------------
// K2 (PDL): width table (independent prologue, overlaps K1) ->
// cudaGridDependencySynchronize -> coalesced flat reduce of partials ->
// 9-label scan over 512 tokens. One block, 512 threads.
// ---------------------------------------------------------------------------
__global__ void __launch_bounds__(512)
rs_kernel(const float* __restrict__ wt,
          const float* __restrict__ W,
          const float* __restrict__ b) {
    __shared__ __align__(16) float sPa[SEQ_LEN * NLAB];  // 18 KB
    __shared__ float tot[16][NLAB];
    __shared__ float carry[16][NLAB];

    const int tid  = threadIdx.x;
    const int lane = tid & 31;
    const int warp = tid >> 5;

    // --- prologue: width projection + reciprocal (inputs only) ---
    if (tid < (MAXW + 1) * NLAB) {
        const int w = tid / NLAB;
        const int l = tid % NLAB;
        const float* wrow = W + (size_t)l * FEAT + 3 * EMB;
        float a = __ldg(b + l);
        #pragma unroll
        for (int k = 0; k < WDIM; k++)
            a += __ldg(wt + w * WDIM + k) * __ldg(wrow + k);
        g_Wb[tid] = make_float2(a, 1.0f / (float)w);   // w=0 never read
    }

    cudaGridDependencySynchronize();      // HW wait for K1 (no polling)

    // --- coalesced reduce: flat float4, lane-consecutive ---
    #pragma unroll
    for (int k = 0; k < Q4; k++) {
        const int pos = tid + k * 512;                // 0..3583
        float4 s = make_float4(0.f, 0.f, 0.f, 0.f);
        #pragma unroll
        for (int c = 0; c < NCHUNK; c++) {
            const float4 v = __ldg(&g_part4[c * FLAT4 + pos]);
            s.x += v.x; s.y += v.y; s.z += v.z; s.w += v.w;
        }
        const int t  = pos / Q4;
        const int j0 = (pos - t * Q4) * 4;
        const float vv[4] = {s.x, s.y, s.z, s.w};
        #pragma unroll
        for (int e = 0; e < 4; e++) {
            const int j = j0 + e;
            if (j < 9)
                reinterpret_cast<float*>(g_S)[(t * NLAB + j) * 2] = vv[e];
            else if (j < 18)
                reinterpret_cast<float*>(g_E)[(t * NLAB + j - 9) * 2] = vv[e];
            else if (j < 27)
                sPa[t * NLAB + (j - 18)] = vv[e];
        }
    }
    __syncthreads();

    // --- 9 parallel scans over 512 tokens (thread = token) ---
    float x[NLAB], a[NLAB];
    #pragma unroll
    for (int l = 0; l < NLAB; l++) { x[l] = sPa[tid * NLAB + l]; a[l] = x[l]; }

    #pragma unroll
    for (int l = 0; l < NLAB; l++) {
        #pragma unroll
        for (int o = 1; o < 32; o <<= 1) {
            const float y = __shfl_up_sync(0xffffffffu, a[l], o);
            if (lane >= o) a[l] += y;
        }
    }
    if (lane == 31) {
        #pragma unroll
        for (int l = 0; l < NLAB; l++) tot[warp][l] = a[l];
    }
    __syncthreads();
    if (tid < NLAB) {
        float r = 0.f;
        #pragma unroll
        for (int w = 0; w < 16; w++) { carry[w][tid] = r; r += tot[w][tid]; }
    }
    __syncthreads();
    #pragma unroll
    for (int l = 0; l < NLAB; l++) {
        const float excl = a[l] - x[l] + carry[warp][l];   // Pc[tid]
        reinterpret_cast<float*>(g_S)[(tid * NLAB + l) * 2 + 1] = excl;
        reinterpret_cast<float*>(g_E)[(tid * NLAB + l) * 2 + 1] = excl;
    }
}

// ---------------------------------------------------------------------------
// K3 (PDL): assemble. Prologue loads indices (inputs only, overlaps K2),
// then HW-sync, then table gathers + coalesced store.
// Block = 288 thr = 32 spans x 9 labels (exact cover).
// ---------------------------------------------------------------------------
__global__ void __launch_bounds__(288)
assemble_kernel(const int* __restrict__ st,
                const int* __restrict__ en,
                const int* __restrict__ wd,
                float* __restrict__ out) {
    const int tid  = threadIdx.x;
    const int sp_l = tid / NLAB;                 // 0..31
    const int l    = tid - sp_l * NLAB;          // 0..8
    const int span = blockIdx.x * 32 + sp_l;

    const int s = __ldg(st + span);              // prologue: inputs only
    const int e = __ldg(en + span);
    const int w = __ldg(wd + span);
    const int is = s * NLAB + l;
    const int ie = e * NLAB + l;
    const int iw = w * NLAB + l;

    cudaGridDependencySynchronize();             // HW wait for K2

    const float2 fs = g_S[is];
    const float2 fe = g_E[ie];
    const float2 fw = g_Wb[iw];
    out[blockIdx.x * 288 + tid] = fs.x + fe.x + (fe.y - fs.y) * fw.y + fw.x;
}

// ---------------------------------------------------------------------------
extern "C" void kernel_launch(void* const* d_in, const int* in_sizes, int n_in,
                              void* d_out, int out_size) {
    const float* seq = (const float*)d_in[0];   // [1,512,768]
    const int*   st  = (const int*)  d_in[1];   // [32768]
    const int*   en  = (const int*)  d_in[2];   // [32768]
    const int*   wd  = (const int*)  d_in[3];   // [32768]
    const float* wt  = (const float*)d_in[4];   // [17,50]
    const float* W   = (const float*)d_in[5];   // [9,2354]
    const float* b   = (const float*)d_in[6];   // [9]
    float* out = (float*)d_out;                 // [32768,9]

    dim3 g1(SEQ_LEN / 8, NCHUNK);               // 384 blocks
    proj_kernel<<<g1, 256>>>(seq, W);

    cudaLaunchAttribute at[1];
    at[0].id = cudaLaunchAttributeProgrammaticStreamSerialization;
    at[0].val.programmaticStreamSerializationAllowed = 1;

    {   // K2 with PDL
        cudaLaunchConfig_t cfg = {};
        cfg.gridDim = dim3(1, 1, 1);
        cfg.blockDim = dim3(512, 1, 1);
        cfg.stream = 0;
        cfg.attrs = at;
        cfg.numAttrs = 1;
        cudaLaunchKernelEx(&cfg, rs_kernel, wt, W, b);
    }
    {   // K3 with PDL
        cudaLaunchConfig_t cfg = {};
        cfg.gridDim = dim3(NSPANS / 32, 1, 1);
        cfg.blockDim = dim3(288, 1, 1);
        cfg.stream = 0;
        cfg.attrs = at;
        cfg.numAttrs = 1;
        cudaLaunchKernelEx(&cfg, assemble_kernel, st, en, wd, out);
    }
}

// round 8
// speedup vs baseline: 1.6724x; 1.4700x over previous
#include <cuda_runtime.h>

// Problem constants (fixed by the reference)
#define SEQ_LEN   512
#define EMB       768
#define NLAB      9
#define FEAT      2354            // 3*768 + 50
#define WDIM      50
#define MAXW      16
#define NSPANS    32768

// Packed tables (allocation-free rule: __device__ globals)
// g_S[t*9+l] = (Ps[t][l], Pc[t][l])   Pc = exclusive prefix of Pa
// g_E[t*9+l] = (Pe[t][l], Pc[t][l])
// g_Wb[w*9+l] = (width_proj + bias, 1/w)
__device__ float2 g_S[SEQ_LEN * NLAB];
__device__ float2 g_E[SEQ_LEN * NLAB];
__device__ float  g_Pa[SEQ_LEN * NLAB];
__device__ float2 g_Wb[(MAXW + 1) * NLAB];

// ---------------------------------------------------------------------------
// K1: direct token projection, NO split-K, NO reduce stage.
// 512 blocks (one token each) x 288 threads (9 warps x 3 dots).
// Seq row staged in smem; W rows read via float2 __ldg (8B-aligned rows);
// W (83 KB) is L1-resident across co-resident blocks. 36 independent LDG.64
// + 72 FMA + 15 SHFL per warp -> high MLP, short critical path.
// ---------------------------------------------------------------------------
__global__ void __launch_bounds__(288)
proj_kernel(const float* __restrict__ seq, const float* __restrict__ W) {
    __shared__ __align__(16) float srow[EMB];

    const int tid  = threadIdx.x;
    const int warp = tid >> 5;          // 0..8
    const int lane = tid & 31;
    const int tok  = blockIdx.x;

    if (tid < EMB / 4) {
        const float4 v = reinterpret_cast<const float4*>(seq + (size_t)tok * EMB)[tid];
        reinterpret_cast<float4*>(srow)[tid] = v;
    }
    __syncthreads();

    // Warp w owns j = 3w, 3w+1, 3w+2  (j -> label l = j%9, slice sl = j/9)
    const int j0 = warp * 3;
    float acc[3] = {0.f, 0.f, 0.f};
    const float* wbase[3];
    #pragma unroll
    for (int i = 0; i < 3; i++) {
        const int j = j0 + i;
        const int l = j % 9, sl = j / 9;
        wbase[i] = W + (size_t)l * FEAT + sl * EMB;
    }

    #pragma unroll
    for (int it = 0; it < 12; it++) {
        const int k = it * 64 + lane * 2;
        const float2 sv = *reinterpret_cast<const float2*>(srow + k);
        #pragma unroll
        for (int i = 0; i < 3; i++) {
            const float2 wv = __ldg(reinterpret_cast<const float2*>(wbase[i] + k));
            acc[i] += sv.x * wv.x + sv.y * wv.y;
        }
    }

    #pragma unroll
    for (int i = 0; i < 3; i++) {
        #pragma unroll
        for (int o = 16; o > 0; o >>= 1)
            acc[i] += __shfl_down_sync(0xffffffffu, acc[i], o);
    }
    if (lane == 0) {
        #pragma unroll
        for (int i = 0; i < 3; i++) {
            const int j = j0 + i;
            const int l = j % 9, sl = j / 9;
            if (sl == 0)
                reinterpret_cast<float*>(g_S)[(tok * NLAB + l) * 2] = acc[i];
            else if (sl == 1)
                reinterpret_cast<float*>(g_E)[(tok * NLAB + l) * 2] = acc[i];
            else
                g_Pa[tok * NLAB + l] = acc[i];
        }
    }
}

// ---------------------------------------------------------------------------
// K2 (PDL): width-table prologue (inputs only, overlaps K1) -> HW grid sync
// -> 9 parallel scans over 512 tokens (one block, 512 threads).
// ---------------------------------------------------------------------------
__global__ void __launch_bounds__(512)
scan_kernel(const float* __restrict__ wt,
            const float* __restrict__ W,
            const float* __restrict__ b) {
    __shared__ float tot[16][NLAB];
    __shared__ float carry[16][NLAB];

    const int tid  = threadIdx.x;
    const int lane = tid & 31;
    const int warp = tid >> 5;

    // prologue: width projection + reciprocal (independent of K1)
    if (tid < (MAXW + 1) * NLAB) {
        const int w = tid / NLAB;
        const int l = tid % NLAB;
        const float* wrow = W + (size_t)l * FEAT + 3 * EMB;
        float a = __ldg(b + l);
        #pragma unroll
        for (int k = 0; k < WDIM; k++)
            a += __ldg(wt + w * WDIM + k) * __ldg(wrow + k);
        g_Wb[tid] = make_float2(a, 1.0f / (float)w);   // w=0 never read
    }

    cudaGridDependencySynchronize();      // HW wait for K1 (no polling, no fence)

    float x[NLAB], a[NLAB];
    #pragma unroll
    for (int l = 0; l < NLAB; l++) { x[l] = g_Pa[tid * NLAB + l]; a[l] = x[l]; }

    #pragma unroll
    for (int l = 0; l < NLAB; l++) {
        #pragma unroll
        for (int o = 1; o < 32; o <<= 1) {
            const float y = __shfl_up_sync(0xffffffffu, a[l], o);
            if (lane >= o) a[l] += y;
        }
    }
    if (lane == 31) {
        #pragma unroll
        for (int l = 0; l < NLAB; l++) tot[warp][l] = a[l];
    }
    __syncthreads();
    if (tid < NLAB) {
        float r = 0.f;
        #pragma unroll
        for (int w = 0; w < 16; w++) { carry[w][tid] = r; r += tot[w][tid]; }
    }
    __syncthreads();
    #pragma unroll
    for (int l = 0; l < NLAB; l++) {
        const float excl = a[l] - x[l] + carry[warp][l];   // Pc[tid]
        reinterpret_cast<float*>(g_S)[(tid * NLAB + l) * 2 + 1] = excl;
        reinterpret_cast<float*>(g_E)[(tid * NLAB + l) * 2 + 1] = excl;
    }
}

// ---------------------------------------------------------------------------
// K3 (PDL): assemble. Prologue loads indices (inputs only, overlaps K2),
// then HW sync, then table gathers + coalesced store.
// Block = 288 thr = 32 spans x 9 labels (exact cover).
// ---------------------------------------------------------------------------
__global__ void __launch_bounds__(288)
assemble_kernel(const int* __restrict__ st,
                const int* __restrict__ en,
                const int* __restrict__ wd,
                float* __restrict__ out) {
    const int tid  = threadIdx.x;
    const int sp_l = tid / NLAB;                 // 0..31
    const int l    = tid - sp_l * NLAB;          // 0..8
    const int span = blockIdx.x * 32 + sp_l;

    const int s = __ldg(st + span);              // prologue: inputs only
    const int e = __ldg(en + span);
    const int w = __ldg(wd + span);
    const int is = s * NLAB + l;
    const int ie = e * NLAB + l;
    const int iw = w * NLAB + l;

    cudaGridDependencySynchronize();             // HW wait for K2

    const float2 fs = g_S[is];
    const float2 fe = g_E[ie];
    const float2 fw = g_Wb[iw];
    out[blockIdx.x * 288 + tid] = fs.x + fe.x + (fe.y - fs.y) * fw.y + fw.x;
}

// ---------------------------------------------------------------------------
extern "C" void kernel_launch(void* const* d_in, const int* in_sizes, int n_in,
                              void* d_out, int out_size) {
    const float* seq = (const float*)d_in[0];   // [1,512,768]
    const int*   st  = (const int*)  d_in[1];   // [32768]
    const int*   en  = (const int*)  d_in[2];   // [32768]
    const int*   wd  = (const int*)  d_in[3];   // [32768]
    const float* wt  = (const float*)d_in[4];   // [17,50]
    const float* W   = (const float*)d_in[5];   // [9,2354]
    const float* b   = (const float*)d_in[6];   // [9]
    float* out = (float*)d_out;                 // [32768,9]

    proj_kernel<<<SEQ_LEN, 288>>>(seq, W);

    cudaLaunchAttribute at[1];
    at[0].id = cudaLaunchAttributeProgrammaticStreamSerialization;
    at[0].val.programmaticStreamSerializationAllowed = 1;

    {   // K2 with PDL
        cudaLaunchConfig_t cfg = {};
        cfg.gridDim = dim3(1, 1, 1);
        cfg.blockDim = dim3(512, 1, 1);
        cfg.stream = 0;
        cfg.attrs = at;
        cfg.numAttrs = 1;
        cudaLaunchKernelEx(&cfg, scan_kernel, wt, W, b);
    }
    {   // K3 with PDL
        cudaLaunchConfig_t cfg = {};
        cfg.gridDim = dim3(NSPANS / 32, 1, 1);
        cfg.blockDim = dim3(288, 1, 1);
        cfg.stream = 0;
        cfg.attrs = at;
        cfg.numAttrs = 1;
        cudaLaunchKernelEx(&cfg, assemble_kernel, st, en, wd, out);
    }
}